// round 7
// baseline (speedup 1.0000x reference)
#include <cuda_runtime.h>
#include <cuda_bf16.h>

#define N_NODES   100000
#define N_EDGES_MAX 1600000
#define N_GRAPHS  256
#define IN_DIM    205
#define HID_DIM   128
#define FC_DIM    64
#define OUT_DIM   2
#define SCAN_BLK  1024

// ---------------- scratch (static device globals; referenced ONLY from device code) ----------------
__device__ __align__(128) float g_h1[(size_t)N_NODES * HID_DIM];  // layer-1 GEMM output H1
__device__ __align__(128) float g_h2[(size_t)N_NODES * HID_DIM];  // layer-2 GEMM output H2
__device__ int   g_degi[N_NODES];
__device__ int   g_rowstart[N_NODES];
__device__ int   g_cursor[N_NODES];
__device__ int   g_blocksum[128];
__device__ int   g_csrc[N_EDGES_MAX];
__device__ float g_ds[N_NODES];
__device__ float g_gsum[N_GRAPHS * HID_DIM];
__device__ float g_gcnt[N_GRAPHS];

// ---------------- zero the small accumulators ----------------
__global__ void zero_kernel() {
    int i = blockIdx.x * blockDim.x + threadIdx.x;
    if (i < N_NODES) g_degi[i] = 0;
    if (i < N_GRAPHS * HID_DIM) g_gsum[i] = 0.0f;
    if (i < N_GRAPHS) g_gcnt[i] = 0.0f;
}

// ---------------- in-degree histogram ----------------
__global__ void hist_kernel(const int* __restrict__ dst, int E) {
    int e = blockIdx.x * blockDim.x + threadIdx.x;
    if (e < E) atomicAdd(&g_degi[dst[e]], 1);
}

// ---------------- scan level 1: per-block exclusive scan + block sums ----------------
__global__ void scan1_kernel() {
    __shared__ int sh[SCAN_BLK];
    int i = blockIdx.x * SCAN_BLK + threadIdx.x;
    int v = (i < N_NODES) ? g_degi[i] : 0;
    sh[threadIdx.x] = v;
    __syncthreads();
    for (int off = 1; off < SCAN_BLK; off <<= 1) {
        int t = (threadIdx.x >= off) ? sh[threadIdx.x - off] : 0;
        __syncthreads();
        sh[threadIdx.x] += t;
        __syncthreads();
    }
    if (i < N_NODES) g_rowstart[i] = sh[threadIdx.x] - v;  // exclusive
    if (threadIdx.x == SCAN_BLK - 1) g_blocksum[blockIdx.x] = sh[threadIdx.x];
}

// -------- scan level 2 fused: PARALLEL block-sum prefix per block (nb <= 128) --------
__global__ void scan3_kernel(const int* __restrict__ batch, int nb) {
    __shared__ int pref[256];
    int t = threadIdx.x;
    int v = (t < nb) ? g_blocksum[t] : 0;
    pref[t] = v;
    __syncthreads();
    for (int off = 1; off < 256; off <<= 1) {
        int u = (t >= off) ? pref[t - off] : 0;
        __syncthreads();
        pref[t] += u;
        __syncthreads();
    }
    int ex = pref[t] - v;   // exclusive
    __syncthreads();
    pref[t] = ex;
    __syncthreads();

    int i = blockIdx.x * blockDim.x + t;
    if (i >= N_NODES) return;
    int rs = g_rowstart[i] + pref[i / SCAN_BLK];
    g_rowstart[i] = rs;
    g_cursor[i] = rs;
    g_ds[i] = rsqrtf((float)g_degi[i] + 1.0f);
    atomicAdd(&g_gcnt[batch[i]], 1.0f);
}

// ---------------- CSR scatter (bucket order irrelevant: sum is commutative) ----------------
__global__ void scatter_kernel(const int* __restrict__ src, const int* __restrict__ dst, int E) {
    int e = blockIdx.x * blockDim.x + threadIdx.x;
    if (e < E) {
        int pos = atomicAdd(&g_cursor[dst[e]], 1);
        g_csrc[pos] = src[e];
    }
}

// ---------------- GEMM (scalar FFMA, proven): OUT = in @ W ----------------
// PRE=false: in = X rows (global), OUT = g_h1.
// PRE=true : in = CSR-aggregate of g_h1 with relu(+bias) built in-block, OUT = g_h2.
// All scratch pointers resolved in DEVICE code (host cannot name __device__ symbols).
// Block: 32 rows x 128 cols, 128 threads, each thread 8 rows x 4 cols, k-quad float4 LDS.
template <int K, bool PRE>
__global__ void __launch_bounds__(128) gemm_kernel(const float* __restrict__ X,
                                                   const float* __restrict__ W,
                                                   const float* __restrict__ bias,
                                                   int N) {
    constexpr int KP = (K + 3) & ~3;
    constexpr int K4 = K & ~3;
    __shared__ float xs[32 * KP];   // 26624B (K=205) or 16384B (K=128)
    float* OUT = PRE ? g_h2 : g_h1;
    int row0 = blockIdx.x * 32;
    int tid = threadIdx.x;

    if (!PRE) {
        for (int idx = tid; idx < 32 * K; idx += 128) {
            int m = idx / K;
            int k = idx - m * K;
            int row = row0 + m;
            xs[m * KP + k] = (row < N) ? X[(size_t)row * K + k] : 0.0f;
        }
    } else {
        // fused layer-1 aggregation: warp w builds rows w*8 .. w*8+7 of the tile
        int lane = tid & 31;
        int w = tid >> 5;
        float4 bv = reinterpret_cast<const float4*>(bias)[lane];
        const float4* __restrict__ hs = reinterpret_cast<const float4*>(g_h1);
#pragma unroll
        for (int i = 0; i < 8; i++) {
            int m = w * 8 + i;
            int node = row0 + m;
            float4 o = make_float4(0.0f, 0.0f, 0.0f, 0.0f);
            if (node < N) {
                float dsd = g_ds[node];
                float4 self = hs[(size_t)node * 32 + lane];
                float4 sum = make_float4(dsd * self.x, dsd * self.y, dsd * self.z, dsd * self.w);
                int start = g_rowstart[node];
                int deg = g_degi[node];
                for (int j0 = 0; j0 < deg; j0 += 32) {
                    int idx = j0 + lane;
                    int myid = (idx < deg) ? g_csrc[start + idx] : 0;
                    float myds = g_ds[myid];
                    int cnt = min(32, deg - j0);
#pragma unroll 4
                    for (int kk = 0; kk < cnt; kk++) {
                        int s = __shfl_sync(0xffffffffu, myid, kk);
                        float dss = __shfl_sync(0xffffffffu, myds, kk);
                        float4 v = hs[(size_t)s * 32 + lane];
                        sum.x = fmaf(dss, v.x, sum.x);
                        sum.y = fmaf(dss, v.y, sum.y);
                        sum.z = fmaf(dss, v.z, sum.z);
                        sum.w = fmaf(dss, v.w, sum.w);
                    }
                }
                o.x = fmaxf(fmaf(sum.x, dsd, bv.x), 0.0f);
                o.y = fmaxf(fmaf(sum.y, dsd, bv.y), 0.0f);
                o.z = fmaxf(fmaf(sum.z, dsd, bv.z), 0.0f);
                o.w = fmaxf(fmaf(sum.w, dsd, bv.w), 0.0f);
            }
            *reinterpret_cast<float4*>(&xs[m * KP + lane * 4]) = o;
        }
    }
    __syncthreads();

    int f0 = (tid & 31) * 4;
    int m0 = (tid >> 5) * 8;

    float acc[8][4];
#pragma unroll
    for (int m = 0; m < 8; m++)
#pragma unroll
        for (int j = 0; j < 4; j++) acc[m][j] = 0.0f;

    const float4* xs4 = reinterpret_cast<const float4*>(xs);

    for (int k = 0; k < K4; k += 4) {
        float4 w0 = *reinterpret_cast<const float4*>(&W[(k + 0) * HID_DIM + f0]);
        float4 w1 = *reinterpret_cast<const float4*>(&W[(k + 1) * HID_DIM + f0]);
        float4 w2 = *reinterpret_cast<const float4*>(&W[(k + 2) * HID_DIM + f0]);
        float4 w3 = *reinterpret_cast<const float4*>(&W[(k + 3) * HID_DIM + f0]);
#pragma unroll
        for (int m = 0; m < 8; m++) {
            float4 xv = xs4[((m0 + m) * KP + k) >> 2];
            acc[m][0] = fmaf(xv.x, w0.x, fmaf(xv.y, w1.x, fmaf(xv.z, w2.x, fmaf(xv.w, w3.x, acc[m][0]))));
            acc[m][1] = fmaf(xv.x, w0.y, fmaf(xv.y, w1.y, fmaf(xv.z, w2.y, fmaf(xv.w, w3.y, acc[m][1]))));
            acc[m][2] = fmaf(xv.x, w0.z, fmaf(xv.y, w1.z, fmaf(xv.z, w2.z, fmaf(xv.w, w3.z, acc[m][2]))));
            acc[m][3] = fmaf(xv.x, w0.w, fmaf(xv.y, w1.w, fmaf(xv.z, w2.w, fmaf(xv.w, w3.w, acc[m][3]))));
        }
    }
    for (int k = K4; k < K; k++) {
        float4 w = *reinterpret_cast<const float4*>(&W[k * HID_DIM + f0]);
#pragma unroll
        for (int m = 0; m < 8; m++) {
            float xv = xs[(m0 + m) * KP + k];
            acc[m][0] = fmaf(xv, w.x, acc[m][0]);
            acc[m][1] = fmaf(xv, w.y, acc[m][1]);
            acc[m][2] = fmaf(xv, w.z, acc[m][2]);
            acc[m][3] = fmaf(xv, w.w, acc[m][3]);
        }
    }

#pragma unroll
    for (int m = 0; m < 8; m++) {
        int row = row0 + m0 + m;
        if (row < N) {
            *reinterpret_cast<float4*>(&OUT[(size_t)row * HID_DIM + f0]) =
                make_float4(acc[m][0], acc[m][1], acc[m][2], acc[m][3]);
        }
    }
}

// ------- final aggregation + pool: relu(ds[d]*(sum ds[s]*H2[s] + ds[d]*H2[d]) + b2) -> gsum -------
__global__ void __launch_bounds__(256) agg_final_kernel(const int* __restrict__ batch,
                                                        const float* __restrict__ b2,
                                                        int n) {
    int node = (blockIdx.x * blockDim.x + threadIdx.x) >> 5;
    int lane = threadIdx.x & 31;
    if (node >= n) return;

    const float4* __restrict__ hs = reinterpret_cast<const float4*>(g_h2);
    float dsd = g_ds[node];
    float4 self = hs[(size_t)node * 32 + lane];
    float4 sum = make_float4(dsd * self.x, dsd * self.y, dsd * self.z, dsd * self.w);

    int start = g_rowstart[node];
    int deg = g_degi[node];

    for (int j0 = 0; j0 < deg; j0 += 32) {
        int idx = j0 + lane;
        int myid = (idx < deg) ? g_csrc[start + idx] : 0;
        float myds = g_ds[myid];
        int cnt = min(32, deg - j0);
#pragma unroll 4
        for (int k = 0; k < cnt; k++) {
            int s = __shfl_sync(0xffffffffu, myid, k);
            float dss = __shfl_sync(0xffffffffu, myds, k);
            float4 v = hs[(size_t)s * 32 + lane];
            sum.x = fmaf(dss, v.x, sum.x);
            sum.y = fmaf(dss, v.y, sum.y);
            sum.z = fmaf(dss, v.z, sum.z);
            sum.w = fmaf(dss, v.w, sum.w);
        }
    }

    float4 bv = reinterpret_cast<const float4*>(b2)[lane];
    float vx = fmaxf(fmaf(sum.x, dsd, bv.x), 0.0f);
    float vy = fmaxf(fmaf(sum.y, dsd, bv.y), 0.0f);
    float vz = fmaxf(fmaf(sum.z, dsd, bv.z), 0.0f);
    float vw = fmaxf(fmaf(sum.w, dsd, bv.w), 0.0f);
    float4* out = reinterpret_cast<float4*>(g_gsum) + batch[node] * 32 + lane;
    asm volatile("red.global.add.v4.f32 [%0], {%1, %2, %3, %4};"
                 :: "l"(out), "f"(vx), "f"(vy), "f"(vz), "f"(vw)
                 : "memory");
}

// ---------------- FC head ----------------
__global__ void __launch_bounds__(64) fc_kernel(const float* __restrict__ Wf1,
                                                const float* __restrict__ bf1,
                                                const float* __restrict__ Wf2,
                                                const float* __restrict__ bf2,
                                                float* __restrict__ out) {
    __shared__ float grow[HID_DIM];
    __shared__ float a[FC_DIM];
    int g = blockIdx.x;
    int t = threadIdx.x;
    float inv = 1.0f / fmaxf(g_gcnt[g], 1.0f);
    grow[t] = g_gsum[g * HID_DIM + t] * inv;
    grow[t + 64] = g_gsum[g * HID_DIM + 64 + t] * inv;
    __syncthreads();
    float acc = bf1[t];
#pragma unroll 8
    for (int k = 0; k < HID_DIM; k++) acc += grow[k] * Wf1[k * FC_DIM + t];
    a[t] = fmaxf(acc, 0.0f);
    __syncthreads();
    if (t < OUT_DIM) {
        float o = bf2[t];
#pragma unroll 8
        for (int j = 0; j < FC_DIM; j++) o += a[j] * Wf2[j * OUT_DIM + t];
        out[g * OUT_DIM + t] = o;
    }
}

// ---------------- fork/join resources ----------------
struct SideStream {
    cudaStream_t s = nullptr;
    cudaEvent_t fork = nullptr, join = nullptr;
    SideStream() {
        if (cudaStreamCreateWithFlags(&s, cudaStreamNonBlocking) != cudaSuccess) { s = nullptr; return; }
        if (cudaEventCreateWithFlags(&fork, cudaEventDisableTiming) != cudaSuccess) { s = nullptr; return; }
        if (cudaEventCreateWithFlags(&join, cudaEventDisableTiming) != cudaSuccess) { s = nullptr; return; }
    }
};
static SideStream& side() { static SideStream ss; return ss; }

// ---------------- launcher ----------------
extern "C" void kernel_launch(void* const* d_in, const int* in_sizes, int n_in,
                              void* d_out, int out_size) {
    const float* x   = (const float*)d_in[0];
    const int* ei    = (const int*)d_in[1];   // [2, E] int32
    const int* batch = (const int*)d_in[2];
    const float* W1  = (const float*)d_in[3];
    const float* b1  = (const float*)d_in[4];
    const float* W2  = (const float*)d_in[5];
    const float* b2  = (const float*)d_in[6];
    const float* Wf1 = (const float*)d_in[7];
    const float* bf1 = (const float*)d_in[8];
    const float* Wf2 = (const float*)d_in[9];
    const float* bf2 = (const float*)d_in[10];
    float* out = (float*)d_out;

    int E = in_sizes[1] / 2;
    int N = in_sizes[2];
    const int* src = ei;
    const int* dst = ei + E;
    int nb = (N_NODES + SCAN_BLK - 1) / SCAN_BLK;

    SideStream& ss = side();
    bool forked = (ss.s != nullptr);
    cudaStream_t cs = forked ? ss.s : (cudaStream_t)0;

    if (forked) {
        cudaEventRecord(ss.fork, 0);
        cudaStreamWaitEvent(ss.s, ss.fork, 0);
    }

    // --- CSR build chain (side stream): independent of GEMM1 ---
    zero_kernel<<<(N_NODES + 255) / 256, 256, 0, cs>>>();
    hist_kernel<<<(E + 255) / 256, 256, 0, cs>>>(dst, E);
    scan1_kernel<<<nb, SCAN_BLK, 0, cs>>>();
    scan3_kernel<<<(N_NODES + 255) / 256, 256, 0, cs>>>(batch, nb);
    scatter_kernel<<<(E + 255) / 256, 256, 0, cs>>>(src, dst, E);
    if (forked) cudaEventRecord(ss.join, ss.s);

    // --- GEMM1 -> g_h1 (no ds dependency) ---
    gemm_kernel<IN_DIM, false><<<(N + 31) / 32, 128>>>(x, W1, nullptr, N);

    if (forked) cudaStreamWaitEvent(0, ss.join, 0);

    // --- fused layer-1 aggregation + GEMM2 -> g_h2 ---
    gemm_kernel<HID_DIM, true><<<(N + 31) / 32, 128>>>(nullptr, W2, b1, N);

    // --- layer-2 aggregation + bias + relu + mean-pool accumulate ---
    int agg_blocks = (int)(((long long)N * 32 + 255) / 256);
    agg_final_kernel<<<agg_blocks, 256>>>(batch, b2, N);

    fc_kernel<<<N_GRAPHS, 64>>>(Wf1, bf1, Wf2, bf2, out);
}